// round 8
// baseline (speedup 1.0000x reference)
#include <cuda_runtime.h>
#include <cuda_bf16.h>

#define B_       16
#define L_       65536
#define H_       64
#define K_       64
#define WARMUP   63
#define LOUT     (L_ - WARMUP)          /* 65473 */
#define TILES_PB 512
#define TOTAL_T  (B_ * TILES_PB)
#define GRID     2048
#define CHUNK    (TOTAL_T / GRID)       /* 4 -> CTA covers 512 rows, b const */
#define TPB      256
#define XR       576                    /* 512 + 64 halo */

#define MMA_BF16(c, a0, a1, a2, a3, b0, b1)                                   \
    asm volatile("mma.sync.aligned.m16n8k16.row.col.f32.bf16.bf16.f32 "       \
                 "{%0,%1,%2,%3}, {%4,%5,%6,%7}, {%8,%9}, {%0,%1,%2,%3};"      \
                 : "+f"((c)[0]), "+f"((c)[1]), "+f"((c)[2]), "+f"((c)[3])     \
                 : "r"(a0), "r"(a1), "r"(a2), "r"(a3), "r"(b0), "r"(b1))

__device__ __forceinline__ unsigned pack_bf16x2(float v0, float v1) {
    __nv_bfloat16 h0 = __float2bfloat16(v0), h1 = __float2bfloat16(v1);
    return (unsigned)__bfloat16_as_ushort(h0) |
           ((unsigned)__bfloat16_as_ushort(h1) << 16);
}

__global__ __launch_bounds__(TPB, 2)
void hankel_fb_hmma_kernel(const float* __restrict__ x,
                           const float* __restrict__ W,
                           const float* __restrict__ bias,
                           float* __restrict__ out,
                           int extra_tail)
{
    __shared__ float  xs[XR];
    __shared__ uint2  xa[XR];       /* {hi_pair, lo_pair} of {x[i], x[i+1]} */
    __shared__ uint4  Wf[32 * 32];  /* fragment-ordered W: (nt*4+ks)*32+lane */
    __shared__ float2 stats[512];   /* {inv, -mu*inv} per row */
    __shared__ float4 skbi[32];     /* {Sk[2p], Sk[2p+1], bias[2p], bias[2p+1]} */

    const int tid  = threadIdx.x;
    const int warp = tid >> 5;
    const int lane = tid & 31;
    const int g    = lane >> 2;
    const int q    = lane & 3;
    const int wp   = warp >> 1;     /* row-group 0..3 (32 rows each) */
    const int nh   = warp & 1;      /* n-half */

    if (blockIdx.x == 0 && tid == 0 && extra_tail > 0) {
        float* p = out + (long long)B_ * LOUT * K_;
        for (int i = 0; i < extra_tail; ++i) p[i] = 63.0f;
    }

    /* ---- one-time: W -> fragment-ordered hi/lo smem ---- */
    #pragma unroll
    for (int j = 0; j < 4; ++j) {
        const int c  = warp * 4 + j;          /* c = nt*4 + ks */
        const int nt = c >> 2, ks = c & 3;
        const int n  = nt * 8 + g;
        const int k  = ks * 16 + 2 * q;
        float2 wa = *(const float2*)&W[n * 64 + k];
        float2 wb = *(const float2*)&W[n * 64 + k + 8];
        float ha0 = __bfloat162float(__float2bfloat16(wa.x));
        float ha1 = __bfloat162float(__float2bfloat16(wa.y));
        float hb0 = __bfloat162float(__float2bfloat16(wb.x));
        float hb1 = __bfloat162float(__float2bfloat16(wb.y));
        uint4 f;
        f.x = pack_bf16x2(ha0, ha1);
        f.y = pack_bf16x2(hb0, hb1);
        f.z = pack_bf16x2(wa.x - ha0, wa.y - ha1);
        f.w = pack_bf16x2(wb.x - hb0, wb.y - hb1);
        Wf[c * 32 + lane] = f;
    }
    if (tid < K_) {
        float s = 0.0f;
        #pragma unroll
        for (int h = 0; h < H_; ++h) s += W[tid * H_ + h];
        float bv = bias[tid];
        ((float*)&skbi[tid >> 1])[(tid & 1) + 0] = s;
        ((float*)&skbi[tid >> 1])[(tid & 1) + 2] = bv;
    }

    const int b   = (blockIdx.x * CHUNK) >> 9;
    const int t0c = ((blockIdx.x * CHUNK) & 511) << 7;
    const float* __restrict__ xb = x + (long long)b * L_;
    float* __restrict__ outb = out + (long long)b * LOUT * K_;

    for (int i = tid; i < XR; i += TPB) {
        int gi = t0c + i;
        xs[i] = (gi < L_) ? xb[gi] : 0.0f;
    }
    __syncthreads();

    for (int i = tid; i < XR; i += TPB) {
        float v0 = xs[i];
        float v1 = (i + 1 < XR) ? xs[i + 1] : 0.0f;
        float h0 = __bfloat162float(__float2bfloat16(v0));
        float h1 = __bfloat162float(__float2bfloat16(v1));
        xa[i] = make_uint2(pack_bf16x2(h0, h1), pack_bf16x2(v0 - h0, v1 - h1));
    }

    /* ---- window stats for all 512 rows (warp shuffle scans) ---- */
    #pragma unroll
    for (int half = 0; half < 2; ++half) {
        const int base = warp * 64 + half * 32;
        float v0 = xs[base + lane], v1 = xs[base + 32 + lane], v2 = xs[base + 64 + lane];
        float s0 = v0, s1 = v1, s2 = v2;
        float p0 = v0 * v0, p1 = v1 * v1, p2 = v2 * v2;
        float q2 = p2;
        #pragma unroll
        for (int o = 1; o < 32; o <<= 1) {
            float u;
            u = __shfl_up_sync(0xffffffffu, s0, o); if (lane >= o) s0 += u;
            u = __shfl_up_sync(0xffffffffu, s1, o); if (lane >= o) s1 += u;
            u = __shfl_up_sync(0xffffffffu, s2, o); if (lane >= o) s2 += u;
            u = __shfl_up_sync(0xffffffffu, p0, o); if (lane >= o) p0 += u;
            u = __shfl_up_sync(0xffffffffu, p1, o); if (lane >= o) p1 += u;
            u = __shfl_up_sync(0xffffffffu, p2, o); if (lane >= o) p2 += u;
        }
        float c0 = __shfl_sync(0xffffffffu, s0, 31);
        float c1 = __shfl_sync(0xffffffffu, s1, 31);
        float d0 = __shfl_sync(0xffffffffu, p0, 31);
        float d1 = __shfl_sync(0xffffffffu, p1, 31);
        float sum = (c0 + c1 + s2 - v2) - (s0 - v0);
        float sq  = (d0 + d1 + p2 - q2) - (p0 - v0 * v0);
        float mu  = sum * (1.0f / 64.0f);
        float var = (sq - sum * mu) * (1.0f / 63.0f);     /* ddof=1 */
        var = fmaxf(var, 0.0f);
        float inv = 1.0f / (sqrtf(var) + 1e-6f);          /* eps on sd */
        stats[base + lane] = make_float2(inv, -mu * inv);
    }
    __syncthreads();

    /* hoist Sk/bias fragments (loop-invariant in (nl,q)) */
    float4 sb[4];
    #pragma unroll
    for (int nl = 0; nl < 4; ++nl) sb[nl] = skbi[(nh * 4 + nl) * 4 + q];

    /* ================== tile loop: minimal L1 traffic ================== */
    #pragma unroll 1
    for (int it = 0; it < CHUNK; ++it) {
        const int rb = it * 128 + wp * 32 + g;

        /* all A fragments for this warp-tile: Hankel sharing across ks & mt */
        uint2 A[11];
        {
            const uint2* xw = &xa[rb + 2 * q];
            #pragma unroll
            for (int i = 0; i < 11; ++i) A[i] = xw[8 * i];
        }

        float acc[2][4][4];
        #pragma unroll
        for (int mt = 0; mt < 2; ++mt)
            #pragma unroll
            for (int nl = 0; nl < 4; ++nl)
                #pragma unroll
                for (int c = 0; c < 4; ++c) acc[mt][nl][c] = 0.0f;

        #pragma unroll
        for (int ks = 0; ks < 4; ++ks) {
            #pragma unroll
            for (int nl = 0; nl < 4; ++nl) {
                uint4 f = Wf[((nh * 4 + nl) * 4 + ks) * 32 + lane];
                #pragma unroll
                for (int mt = 0; mt < 2; ++mt) {
                    const int i0 = 2 * ks + 2 * mt;
                    MMA_BF16(acc[mt][nl], A[i0].x, A[i0+1].x, A[i0+1].x, A[i0+2].x, f.x, f.y);
                    MMA_BF16(acc[mt][nl], A[i0].x, A[i0+1].x, A[i0+1].x, A[i0+2].x, f.z, f.w);
                    MMA_BF16(acc[mt][nl], A[i0].y, A[i0+1].y, A[i0+1].y, A[i0+2].y, f.x, f.y);
                }
            }
        }

        /* ---- epilogue ---- */
        #pragma unroll
        for (int mt = 0; mt < 2; ++mt) {
            #pragma unroll
            for (int rr = 0; rr < 2; ++rr) {
                const int rc = it * 128 + wp * 32 + mt * 16 + rr * 8 + g;
                const int t  = t0c + rc;
                if (t < LOUT) {
                    const float2 st = stats[rc];
                    float* o = outb + (long long)t * K_ + nh * 32 + q * 2;
                    #pragma unroll
                    for (int nl = 0; nl < 4; ++nl) {
                        float2 res;
                        res.x = fmaxf(fmaf(acc[mt][nl][rr * 2 + 0], st.x,
                                           fmaf(st.y, sb[nl].x, sb[nl].z)), 0.0f);
                        res.y = fmaxf(fmaf(acc[mt][nl][rr * 2 + 1], st.x,
                                           fmaf(st.y, sb[nl].y, sb[nl].w)), 0.0f);
                        *(float2*)(o + nl * 8) = res;
                    }
                }
            }
        }
    }
}

extern "C" void kernel_launch(void* const* d_in, const int* in_sizes, int n_in,
                              void* d_out, int out_size)
{
    const float* x  = (const float*)d_in[0];
    const float* W  = (const float*)d_in[1];
    const float* bb = (const float*)d_in[2];
    float* out = (float*)d_out;

    long long n_main = (long long)B_ * LOUT * K_;
    int extra = (int)((long long)out_size - n_main);
    if (extra < 0) extra = 0;

    hankel_fb_hmma_kernel<<<GRID, TPB>>>(x, W, bb, out, extra);
}

// round 9
// speedup vs baseline: 1.2621x; 1.2621x over previous
#include <cuda_runtime.h>
#include <cuda_bf16.h>

#define B_       16
#define L_       65536
#define H_       64
#define K_       64
#define WARMUP   63
#define LOUT     (L_ - WARMUP)          /* 65473 */
#define TILES_PB 512
#define TOTAL_T  (B_ * TILES_PB)
#define CHUNK    8                      /* tiles per CTA -> 1024 rows */
#define GRID     (TOTAL_T / CHUNK)      /* 1024 */
#define TPB      256
#define NROWS    (CHUNK * 128)          /* 1024 */
#define XR       (NROWS + 64)           /* 1088 */

#define MMA_BF16(c, a0, a1, a2, a3, b0, b1)                                   \
    asm volatile("mma.sync.aligned.m16n8k16.row.col.f32.bf16.bf16.f32 "       \
                 "{%0,%1,%2,%3}, {%4,%5,%6,%7}, {%8,%9}, {%0,%1,%2,%3};"      \
                 : "+f"((c)[0]), "+f"((c)[1]), "+f"((c)[2]), "+f"((c)[3])     \
                 : "r"(a0), "r"(a1), "r"(a2), "r"(a3), "r"(b0), "r"(b1))

__device__ __forceinline__ unsigned pack_bf16x2(float v0, float v1) {
    __nv_bfloat16 h0 = __float2bfloat16(v0), h1 = __float2bfloat16(v1);
    return (unsigned)__bfloat16_as_ushort(h0) |
           ((unsigned)__bfloat16_as_ushort(h1) << 16);
}

__global__ __launch_bounds__(TPB, 2)
void hankel_fb_hmma_kernel(const float* __restrict__ x,
                           const float* __restrict__ W,
                           const float* __restrict__ bias,
                           float* __restrict__ out,
                           int extra_tail)
{
    __shared__ float  xs[XR];
    __shared__ uint2  xa[XR];        /* {hi_pair, lo_pair} of {x[i], x[i+1]} */
    __shared__ uint4  Wf[32 * 32];   /* fragment-ordered W */
    __shared__ float2 stats[NROWS];  /* {inv, -mu*inv} per row */
    __shared__ float4 skbi[32];

    const int tid  = threadIdx.x;
    const int warp = tid >> 5;
    const int lane = tid & 31;
    const int g    = lane >> 2;
    const int q    = lane & 3;
    const int wp   = warp >> 1;
    const int nh   = warp & 1;

    if (blockIdx.x == 0 && tid == 0 && extra_tail > 0) {
        float* p = out + (long long)B_ * LOUT * K_;
        for (int i = 0; i < extra_tail; ++i) p[i] = 63.0f;
    }

    /* ---- one-time: W -> fragment-ordered hi/lo smem ---- */
    #pragma unroll
    for (int j = 0; j < 4; ++j) {
        const int c  = warp * 4 + j;
        const int nt = c >> 2, ks = c & 3;
        const int n  = nt * 8 + g;
        const int k  = ks * 16 + 2 * q;
        float2 wa = *(const float2*)&W[n * 64 + k];
        float2 wb = *(const float2*)&W[n * 64 + k + 8];
        float ha0 = __bfloat162float(__float2bfloat16(wa.x));
        float ha1 = __bfloat162float(__float2bfloat16(wa.y));
        float hb0 = __bfloat162float(__float2bfloat16(wb.x));
        float hb1 = __bfloat162float(__float2bfloat16(wb.y));
        uint4 f;
        f.x = pack_bf16x2(ha0, ha1);
        f.y = pack_bf16x2(hb0, hb1);
        f.z = pack_bf16x2(wa.x - ha0, wa.y - ha1);
        f.w = pack_bf16x2(wb.x - hb0, wb.y - hb1);
        Wf[c * 32 + lane] = f;
    }
    if (tid < K_) {
        float s = 0.0f;
        #pragma unroll
        for (int h = 0; h < H_; ++h) s += W[tid * H_ + h];
        float bv = bias[tid];
        ((float*)&skbi[tid >> 1])[(tid & 1) + 0] = s;
        ((float*)&skbi[tid >> 1])[(tid & 1) + 2] = bv;
    }

    const int gidx = blockIdx.x * CHUNK;
    const int b    = gidx >> 9;
    const int t0c  = (gidx & 511) << 7;
    const float* __restrict__ xb = x + (long long)b * L_;
    float* __restrict__ outb = out + (long long)b * LOUT * K_;

    for (int i = tid; i < XR; i += TPB) {
        int gi = t0c + i;
        xs[i] = (gi < L_) ? xb[gi] : 0.0f;
    }
    __syncthreads();

    for (int i = tid; i < XR; i += TPB) {
        float v0 = xs[i];
        float v1 = (i + 1 < XR) ? xs[i + 1] : 0.0f;
        float h0 = __bfloat162float(__float2bfloat16(v0));
        float h1 = __bfloat162float(__float2bfloat16(v1));
        xa[i] = make_uint2(pack_bf16x2(h0, h1), pack_bf16x2(v0 - h0, v1 - h1));
    }

    /* ---- window stats for all rows (warp shuffle scans, 4 per warp) ---- */
    #pragma unroll
    for (int half = 0; half < 4; ++half) {
        const int base = warp * 128 + half * 32;
        float v0 = xs[base + lane], v1 = xs[base + 32 + lane], v2 = xs[base + 64 + lane];
        float s0 = v0, s1 = v1, s2 = v2;
        float p0 = v0 * v0, p1 = v1 * v1, p2 = v2 * v2;
        float q2 = p2;
        #pragma unroll
        for (int o = 1; o < 32; o <<= 1) {
            float u;
            u = __shfl_up_sync(0xffffffffu, s0, o); if (lane >= o) s0 += u;
            u = __shfl_up_sync(0xffffffffu, s1, o); if (lane >= o) s1 += u;
            u = __shfl_up_sync(0xffffffffu, s2, o); if (lane >= o) s2 += u;
            u = __shfl_up_sync(0xffffffffu, p0, o); if (lane >= o) p0 += u;
            u = __shfl_up_sync(0xffffffffu, p1, o); if (lane >= o) p1 += u;
            u = __shfl_up_sync(0xffffffffu, p2, o); if (lane >= o) p2 += u;
        }
        float c0 = __shfl_sync(0xffffffffu, s0, 31);
        float c1 = __shfl_sync(0xffffffffu, s1, 31);
        float d0 = __shfl_sync(0xffffffffu, p0, 31);
        float d1 = __shfl_sync(0xffffffffu, p1, 31);
        float sum = (c0 + c1 + s2 - v2) - (s0 - v0);
        float sq  = (d0 + d1 + p2 - q2) - (p0 - v0 * v0);
        float mu  = sum * (1.0f / 64.0f);
        float var = (sq - sum * mu) * (1.0f / 63.0f);     /* ddof=1 */
        var = fmaxf(var, 0.0f);
        float inv = 1.0f / (sqrtf(var) + 1e-6f);          /* eps on sd */
        stats[base + lane] = make_float2(inv, -mu * inv);
    }
    __syncthreads();

    float4 sb[4];
    #pragma unroll
    for (int nl = 0; nl < 4; ++nl) sb[nl] = skbi[(nh * 4 + nl) * 4 + q];

    /* ============ tile loop: unroll 2 for cross-tile ILP ============ */
    #pragma unroll 2
    for (int it = 0; it < CHUNK; ++it) {
        const int rb = it * 128 + wp * 32 + g;

        uint2 A[11];
        {
            const uint2* xw = &xa[rb + 2 * q];
            #pragma unroll
            for (int i = 0; i < 11; ++i) A[i] = xw[8 * i];
        }

        float acc[2][4][4];
        #pragma unroll
        for (int mt = 0; mt < 2; ++mt)
            #pragma unroll
            for (int nl = 0; nl < 4; ++nl)
                #pragma unroll
                for (int c = 0; c < 4; ++c) acc[mt][nl][c] = 0.0f;

        #pragma unroll
        for (int ks = 0; ks < 4; ++ks) {
            #pragma unroll
            for (int nl = 0; nl < 4; ++nl) {
                uint4 f = Wf[((nh * 4 + nl) * 4 + ks) * 32 + lane];
                #pragma unroll
                for (int mt = 0; mt < 2; ++mt) {
                    const int i0 = 2 * ks + 2 * mt;
                    MMA_BF16(acc[mt][nl], A[i0].x, A[i0+1].x, A[i0+1].x, A[i0+2].x, f.x, f.y);
                    MMA_BF16(acc[mt][nl], A[i0].x, A[i0+1].x, A[i0+1].x, A[i0+2].x, f.z, f.w);
                    MMA_BF16(acc[mt][nl], A[i0].y, A[i0+1].y, A[i0+1].y, A[i0+2].y, f.x, f.y);
                }
            }
        }

        #pragma unroll
        for (int mt = 0; mt < 2; ++mt) {
            #pragma unroll
            for (int rr = 0; rr < 2; ++rr) {
                const int rc = it * 128 + wp * 32 + mt * 16 + rr * 8 + g;
                const int t  = t0c + rc;
                if (t < LOUT) {
                    const float2 st = stats[rc];
                    float* o = outb + (long long)t * K_ + nh * 32 + q * 2;
                    #pragma unroll
                    for (int nl = 0; nl < 4; ++nl) {
                        float2 res;
                        res.x = fmaxf(fmaf(acc[mt][nl][rr * 2 + 0], st.x,
                                           fmaf(st.y, sb[nl].x, sb[nl].z)), 0.0f);
                        res.y = fmaxf(fmaf(acc[mt][nl][rr * 2 + 1], st.x,
                                           fmaf(st.y, sb[nl].y, sb[nl].w)), 0.0f);
                        *(float2*)(o + nl * 8) = res;
                    }
                }
            }
        }
    }
}

extern "C" void kernel_launch(void* const* d_in, const int* in_sizes, int n_in,
                              void* d_out, int out_size)
{
    const float* x  = (const float*)d_in[0];
    const float* W  = (const float*)d_in[1];
    const float* bb = (const float*)d_in[2];
    float* out = (float*)d_out;

    long long n_main = (long long)B_ * LOUT * K_;
    int extra = (int)((long long)out_size - n_main);
    if (extra < 0) extra = 0;

    hankel_fb_hmma_kernel<<<GRID, TPB>>>(x, W, bb, out, extra);
}